// round 1
// baseline (speedup 1.0000x reference)
#include <cuda_runtime.h>
#include <math.h>

#define NN 4000      // nodes
#define NE 60000     // edges
#define MDIM 16
#define CDIM 64
#define HDIM 64
#define NHEADS 8
#define CEDIM 32
#define EPB 4        // edges per block (64 threads per edge)

// -------- scratch (static device arrays; no allocation APIs) --------
__device__ float g_logits[NE * NHEADS];
__device__ float g_expsum[NN * NHEADS];
__device__ float g_U[2 * 64 * 8];      // [set][h][head]
__device__ int   g_mask[NN];

struct ParSet {
    const float *emb_s, *emb_t, *w_d, *We, *Ws, *Wt, *Wa, *va, *Wv, *Wo;
};
struct Par2 { ParSet s[2]; };

// -------- mask dtype sniffing + normalization --------
// noise_mask may arrive as bool(u8), int32, or float32. Reading the first 4000
// bytes is always safe (min buffer = 4000 B). Distinguish:
//   float32: some byte > 1 (0x80 / 0x3f in 1.0f)
//   uint8  : bytes at idx%4==1 contain some 1s (P(all zero) ~ 2^-1000)
//   int32  : bytes at idx%4!=0 are all zero, max byte <= 1
__global__ void k_mask(const void* nm) {
    __shared__ int s_max, s_s1;
    if (threadIdx.x == 0) { s_max = 0; s_s1 = 0; }
    __syncthreads();
    const unsigned char* bp = (const unsigned char*)nm;
    int lm = 0, ls = 0;
    for (int i = threadIdx.x; i < NN; i += blockDim.x) {
        int v = bp[i];
        if (v > lm) lm = v;
        if ((i & 3) == 1) ls += v;
    }
    atomicMax(&s_max, lm);
    atomicAdd(&s_s1, ls);
    __syncthreads();
    int mode = (s_max > 1) ? 2 : (s_s1 > 0 ? 0 : 1); // 0=u8 1=i32 2=f32
    for (int n = threadIdx.x; n < NN; n += blockDim.x) {
        int v;
        if (mode == 0)      v = (bp[n] != 0);
        else if (mode == 1) v = (((const int*)nm)[n] != 0);
        else                v = (((const float*)nm)[n] != 0.0f);
        g_mask[n] = v;
    }
}

// -------- zero expsum + out, precompute U = Wv x Wo folded per head --------
__global__ void k_prep(const float* WvF, const float* WoF,
                       const float* WvD, const float* WoD, float* out) {
    int t = blockIdx.x * blockDim.x + threadIdx.x;
    if (t < NN * NHEADS) g_expsum[t] = 0.0f;
    if (t < NN * 3)      out[t] = 0.0f;
    if (t < 1024) {
        int set = t >> 9, r = t & 511, h = r >> 3, hd = r & 7;
        const float* Wv = set ? WvD : WvF;
        const float* Wo = set ? WoD : WoF;
        float s = 0.0f;
        #pragma unroll
        for (int vc = 0; vc < 8; vc++)
            s += Wv[h * 64 + hd * 8 + vc] * Wo[hd * 8 + vc];
        g_U[t] = s;
    }
}

// -------- pass 1: per-edge attention logits + exp-sum scatter --------
__global__ __launch_bounds__(64 * EPB)
void k_pass1(const float* __restrict__ x, const int* __restrict__ zn,
             const float* __restrict__ dist, const int* __restrict__ ei,
             const float* __restrict__ wig, Par2 P) {
    __shared__ float s_xs0[EPB][64], s_xt0[EPB][64], s_ev[EPB][32],
                     s_f0[EPB][64], s_av[EPB][64];
    int li = threadIdx.x >> 6;          // edge slot in block
    int h  = threadIdx.x & 63;          // hidden index
    int eg = blockIdx.x * EPB + li;     // NE divisible by EPB

    int src = ei[eg], dst = ei[NE + eg];
    int b = g_mask[dst];
    const ParSet& pp = P.s[b];

    const float* D0 = wig + (size_t)eg * 256;         // wigner row m=0
    const float* xs = x + (size_t)src * (MDIM * CDIM);
    const float* xt = x + (size_t)dst * (MDIM * CDIM);

    // xs0[c] = sum_n D0[n]*x[src][n,c]  (c = h)
    float a0 = 0.0f, a1 = 0.0f;
    #pragma unroll
    for (int n = 0; n < 16; n++) {
        float d = D0[n];
        a0 += d * xs[n * 64 + h];
        a1 += d * xt[n * 64 + h];
    }
    s_xs0[li][h] = a0;
    s_xt0[li][h] = a1;

    // edge scalar embedding (silu)
    if (h < 32) {
        float z = dist[eg] * pp.w_d[h] + pp.emb_s[zn[src] * 32 + h]
                                       + pp.emb_t[zn[dst] * 32 + h];
        s_ev[li][h] = z / (1.0f + expf(-z));
    }
    __syncthreads();

    // f0[h] = xs0 @ Ws[:,h] + xt0 @ Wt[:,h] + ev @ We[:,h]
    float f0 = 0.0f;
    #pragma unroll 8
    for (int c = 0; c < 64; c++)
        f0 += s_xs0[li][c] * pp.Ws[c * 64 + h] + s_xt0[li][c] * pp.Wt[c * 64 + h];
    #pragma unroll 8
    for (int ce = 0; ce < 32; ce++)
        f0 += s_ev[li][ce] * pp.We[ce * 64 + h];
    s_f0[li][h] = f0;
    __syncthreads();

    // a = leaky_relu(f0 @ Wa, 0.2) * va  (flattened heads x A)
    float aa = 0.0f;
    #pragma unroll 8
    for (int c = 0; c < 64; c++)
        aa += s_f0[li][c] * pp.Wa[c * 64 + h];
    aa = (aa > 0.0f) ? aa : 0.2f * aa;
    s_av[li][h] = aa * pp.va[h];
    __syncthreads();

    if (h < 8) {
        float lg = 0.0f;
        #pragma unroll
        for (int j = 0; j < 8; j++) lg += s_av[li][h * 8 + j];
        g_logits[eg * 8 + h] = lg;
        atomicAdd(&g_expsum[dst * 8 + h], expf(lg));
    }
}

// -------- pass 2: alpha, folded value path, scatter to out --------
__global__ __launch_bounds__(64 * EPB)
void k_pass2(const float* __restrict__ x, const int* __restrict__ zn,
             const float* __restrict__ dist, const int* __restrict__ ei,
             const float* __restrict__ wig, Par2 P, float* __restrict__ out) {
    __shared__ float s_al[EPB][8], s_ev[EPB][32], s_p[EPB][64], s_red[EPB][8];
    int li = threadIdx.x >> 6;
    int h  = threadIdx.x & 63;
    int eg = blockIdx.x * EPB + li;

    int src = ei[eg], dst = ei[NE + eg];
    int b = g_mask[dst];
    const ParSet& pp = P.s[b];

    if (h < 8)
        s_al[li][h] = expf(g_logits[eg * 8 + h]) / (g_expsum[dst * 8 + h] + 1e-9f);
    if (h < 32) {
        float z = dist[eg] * pp.w_d[h] + pp.emb_s[zn[src] * 32 + h]
                                       + pp.emb_t[zn[dst] * 32 + h];
        s_ev[li][h] = z / (1.0f + expf(-z));
    }
    __syncthreads();

    // p[h] = sum_hd U[h,hd]*alpha[hd]
    const float* Ub = g_U + b * 512;
    float ph = 0.0f;
    #pragma unroll
    for (int hd = 0; hd < 8; hd++) ph += Ub[h * 8 + hd] * s_al[li][hd];
    s_p[li][h] = ph;

    // inj[h] = ev @ We[:,h]   (m=0 injection)
    float inj = 0.0f;
    #pragma unroll 8
    for (int ce = 0; ce < 32; ce++)
        inj += s_ev[li][ce] * pp.We[ce * 64 + h];
    __syncthreads();

    // Ps[c] = sum_h Ws[c,h]*p[h], Pt[c] likewise  (c = h)
    float Psc = 0.0f, Ptc = 0.0f;
    #pragma unroll 8
    for (int hh = 0; hh < 64; hh++) {
        float pv = s_p[li][hh];
        Psc += pp.Ws[h * 64 + hh] * pv;
        Ptc += pp.Wt[h * 64 + hh] * pv;
    }

    // partial contributions for output rows r=1..3 (orthogonality fold)
    const float* xs1 = x + (size_t)src * (MDIM * CDIM) + 64;  // row m=1
    const float* xt1 = x + (size_t)dst * (MDIM * CDIM) + 64;
    float p0 = xs1[h] * Psc + xt1[h] * Ptc;
    float p1 = xs1[64 + h] * Psc + xt1[64 + h] * Ptc;
    float p2 = xs1[128 + h] * Psc + xt1[128 + h] * Ptc;
    float p3 = ph * inj;                                      // pinj partial

    // reduce 4 scalars across the 64-thread group (2 full warps)
    #pragma unroll
    for (int off = 16; off; off >>= 1) {
        p0 += __shfl_down_sync(0xffffffffu, p0, off);
        p1 += __shfl_down_sync(0xffffffffu, p1, off);
        p2 += __shfl_down_sync(0xffffffffu, p2, off);
        p3 += __shfl_down_sync(0xffffffffu, p3, off);
    }
    int lane = threadIdx.x & 31;
    int w2 = (h >> 5) & 1;
    if (lane == 0) {
        s_red[li][w2 * 4 + 0] = p0;
        s_red[li][w2 * 4 + 1] = p1;
        s_red[li][w2 * 4 + 2] = p2;
        s_red[li][w2 * 4 + 3] = p3;
    }
    __syncthreads();
    if (h == 0) {
        float o0 = s_red[li][0] + s_red[li][4];
        float o1 = s_red[li][1] + s_red[li][5];
        float o2 = s_red[li][2] + s_red[li][6];
        float pinj = s_red[li][3] + s_red[li][7];
        const float* D0 = wig + (size_t)eg * 256;
        o0 += pinj * D0[1];
        o1 += pinj * D0[2];
        o2 += pinj * D0[3];
        atomicAdd(&out[dst * 3 + 0], o0);
        atomicAdd(&out[dst * 3 + 1], o1);
        atomicAdd(&out[dst * 3 + 2], o2);
    }
}

extern "C" void kernel_launch(void* const* d_in, const int* in_sizes, int n_in,
                              void* d_out, int out_size) {
    const float* x    = (const float*)d_in[0];
    const int*   zn   = (const int*)d_in[1];
    const float* dist = (const float*)d_in[2];
    const int*   ei   = (const int*)d_in[3];
    const void*  nm   = d_in[4];
    const float* wig  = (const float*)d_in[5];

    Par2 P;
    for (int s = 0; s < 2; s++) {
        int base = 6 + s * 10;
        P.s[s].emb_s = (const float*)d_in[base + 0];
        P.s[s].emb_t = (const float*)d_in[base + 1];
        P.s[s].w_d   = (const float*)d_in[base + 2];
        P.s[s].We    = (const float*)d_in[base + 3];
        P.s[s].Ws    = (const float*)d_in[base + 4];
        P.s[s].Wt    = (const float*)d_in[base + 5];
        P.s[s].Wa    = (const float*)d_in[base + 6];
        P.s[s].va    = (const float*)d_in[base + 7];
        P.s[s].Wv    = (const float*)d_in[base + 8];
        P.s[s].Wo    = (const float*)d_in[base + 9];
    }
    float* out = (float*)d_out;

    k_mask<<<1, 1024>>>(nm);
    k_prep<<<(NN * NHEADS + 255) / 256, 256>>>(P.s[0].Wv, P.s[0].Wo,
                                               P.s[1].Wv, P.s[1].Wo, out);
    k_pass1<<<NE / EPB, 64 * EPB>>>(x, zn, dist, ei, wig, P);
    k_pass2<<<NE / EPB, 64 * EPB>>>(x, zn, dist, ei, wig, P, out);
}

// round 3
// speedup vs baseline: 10.3289x; 10.3289x over previous
#include <cuda_runtime.h>
#include <math.h>

#define NN 4000
#define NE 60000
#define MDIM 16
#define CDIM 64
#define HDIM 64
#define NHEADS 8
#define CEDIM 32

// ---------------- scratch ----------------
__device__ float g_A[NN * 3 * 1024];    // [n][part][16][64] part: 0=As set0,1=As set1,2=At own
__device__ float g_Y3[NN * 3 * 192];    // [n][wpart][3][64]  wpart: 0=Ys set0,1=Ys set1,2=Yt own
__device__ float g_WA[2][4096];         // Ws@Wa per set
__device__ float g_WTA[2][4096];        // Wt@Wa per set
__device__ float g_WeA[2][2048];        // We@Wa per set
__device__ float g_Ut[2][512];          // [set][head][h]  U transposed
__device__ float g_eexp[NE * NHEADS];   // exp(logit)
__device__ float g_expsum[NN * NHEADS];
__device__ int   g_mask[NN];

struct ParSet {
    const float *emb_s, *emb_t, *w_d, *We, *Ws, *Wt, *Wa, *va, *Wv, *Wo;
};
struct Par2 { ParSet s[2]; };

// ---------------- mask dtype sniff (bool/int32/float32) ----------------
__global__ void k_mask(const void* nm) {
    __shared__ int s_max, s_s1;
    if (threadIdx.x == 0) { s_max = 0; s_s1 = 0; }
    __syncthreads();
    const unsigned char* bp = (const unsigned char*)nm;
    int lm = 0, ls = 0;
    for (int i = threadIdx.x; i < NN; i += blockDim.x) {
        int v = bp[i];
        if (v > lm) lm = v;
        if ((i & 3) == 1) ls += v;
    }
    atomicMax(&s_max, lm);
    atomicAdd(&s_s1, ls);
    __syncthreads();
    int mode = (s_max > 1) ? 2 : (s_s1 > 0 ? 0 : 1);
    for (int n = threadIdx.x; n < NN; n += blockDim.x) {
        int v;
        if (mode == 0)      v = (bp[n] != 0);
        else if (mode == 1) v = (((const int*)nm)[n] != 0);
        else                v = (((const float*)nm)[n] != 0.0f);
        g_mask[n] = v;
    }
}

// ---------------- tiny weight folds + zeroing ----------------
__global__ void k_small(Par2 P, float* out) {
    int tid = blockIdx.x * blockDim.x + threadIdx.x;
    int stride = gridDim.x * blockDim.x;
    // WA / WTA: 4 mats x 64 x 64
    for (int i = tid; i < 16384; i += stride) {
        int mat = i >> 12, c = (i >> 6) & 63, j = i & 63;
        int set = mat & 1;
        const float* W  = (mat < 2) ? P.s[set].Ws : P.s[set].Wt;
        const float* Wa = P.s[set].Wa;
        float s = 0.0f;
        for (int h = 0; h < 64; h++) s += W[c * 64 + h] * Wa[h * 64 + j];
        if (mat < 2) g_WA[set][c * 64 + j] = s;
        else         g_WTA[set][c * 64 + j] = s;
    }
    // WeA: 2 x 32 x 64
    for (int i = tid; i < 4096; i += stride) {
        int set = i >> 11, ce = (i >> 6) & 31, j = i & 63;
        const float* We = P.s[set].We;
        const float* Wa = P.s[set].Wa;
        float s = 0.0f;
        for (int h = 0; h < 64; h++) s += We[ce * 64 + h] * Wa[h * 64 + j];
        g_WeA[set][ce * 64 + j] = s;
    }
    // Ut: 2 x 8 x 64
    for (int i = tid; i < 1024; i += stride) {
        int set = i >> 9, r = i & 511, hd = r >> 6, h = r & 63;
        const float* Wv = P.s[set].Wv;
        const float* Wo = P.s[set].Wo;
        float s = 0.0f;
        #pragma unroll
        for (int vc = 0; vc < 8; vc++)
            s += Wv[h * 64 + hd * 8 + vc] * Wo[hd * 8 + vc];
        g_Ut[set][hd * 64 + h] = s;
    }
    for (int i = tid; i < NN * NHEADS; i += stride) g_expsum[i] = 0.0f;
    for (int i = tid; i < NN * 3; i += stride) out[i] = 0.0f;
}

// ---------------- per-node GEMM: A = X@(W@Wa), Y3 = X[1:4]@W ----------------
__global__ __launch_bounds__(256)
void k_node(const float* __restrict__ x, Par2 P) {
    __shared__ float Xs[64 * 20];           // [c][m] padded rows of 20
    int n = blockIdx.x;
    int tid = threadIdx.x;
    int bn = g_mask[n];

    // stage X transposed: Xs[c*20+m] = x[n][m][c]
    for (int i = tid; i < 1024; i += 256) {
        int m = i >> 6, c = i & 63;
        Xs[c * 20 + m] = x[(size_t)n * 1024 + i];
    }
    __syncthreads();

    int mq = tid >> 6;          // 0..3
    int q  = tid & 63;
    int part = q >> 4;          // 0..3
    int h4 = (q & 15) * 4;

    if (part < 3) {
        const float* Wp = (part == 0) ? g_WA[0] : (part == 1) ? g_WA[1] : g_WTA[bn];
        float4 acc0 = {0,0,0,0}, acc1 = {0,0,0,0}, acc2 = {0,0,0,0}, acc3 = {0,0,0,0};
        #pragma unroll 8
        for (int k = 0; k < 64; k++) {
            float4 xa = *(const float4*)&Xs[k * 20 + mq * 4];
            float4 w  = __ldg((const float4*)(Wp + k * 64 + h4));
            acc0.x += xa.x * w.x; acc0.y += xa.x * w.y; acc0.z += xa.x * w.z; acc0.w += xa.x * w.w;
            acc1.x += xa.y * w.x; acc1.y += xa.y * w.y; acc1.z += xa.y * w.z; acc1.w += xa.y * w.w;
            acc2.x += xa.z * w.x; acc2.y += xa.z * w.y; acc2.z += xa.z * w.z; acc2.w += xa.z * w.w;
            acc3.x += xa.w * w.x; acc3.y += xa.w * w.y; acc3.z += xa.w * w.z; acc3.w += xa.w * w.w;
        }
        float* dst = g_A + (size_t)n * 3072 + part * 1024 + (mq * 4) * 64 + h4;
        *(float4*)(dst)       = acc0;
        *(float4*)(dst + 64)  = acc1;
        *(float4*)(dst + 128) = acc2;
        *(float4*)(dst + 192) = acc3;
    } else if (mq < 3) {
        // Y3: wpart = mq; rows m=1..3 with raw Ws/Wt
        const float* Wr = (mq == 0) ? P.s[0].Ws : (mq == 1) ? P.s[1].Ws : P.s[bn].Wt;
        float4 acc0 = {0,0,0,0}, acc1 = {0,0,0,0}, acc2 = {0,0,0,0};
        #pragma unroll 8
        for (int k = 0; k < 64; k++) {
            float4 xa = *(const float4*)&Xs[k * 20];   // m0..m3; use y,z,w
            float4 w  = __ldg((const float4*)(Wr + k * 64 + h4));
            acc0.x += xa.y * w.x; acc0.y += xa.y * w.y; acc0.z += xa.y * w.z; acc0.w += xa.y * w.w;
            acc1.x += xa.z * w.x; acc1.y += xa.z * w.y; acc1.z += xa.z * w.z; acc1.w += xa.z * w.w;
            acc2.x += xa.w * w.x; acc2.y += xa.w * w.y; acc2.z += xa.w * w.z; acc2.w += xa.w * w.w;
        }
        float* dst = g_Y3 + (size_t)n * 576 + mq * 192 + h4;
        *(float4*)(dst)       = acc0;
        *(float4*)(dst + 64)  = acc1;
        *(float4*)(dst + 128) = acc2;
    }
}

// ---------------- pass 1: logits + exp-sum ----------------
__global__ __launch_bounds__(256)
void k_pass1(const int* __restrict__ zn, const float* __restrict__ dist,
             const int* __restrict__ ei, const float* __restrict__ wig, Par2 P) {
    __shared__ float s_WeA[2 * 2048];     // 16KB total (both sets)
    int tid = threadIdx.x;
    // flat copy of g_WeA (exactly 4096 floats)
    {
        const float* srcp = &g_WeA[0][0];
        for (int i = tid * 4; i < 4096; i += 1024)
            *(float4*)(s_WeA + i) = __ldg((const float4*)(srcp + i));
    }
    __syncthreads();

    int l  = tid & 31;
    int wid = tid >> 5;
    int le = l >> 4;
    int q  = l & 15;
    int eg = blockIdx.x * 16 + wid * 2 + le;

    int src = ei[eg], dst = ei[NE + eg];
    int b = g_mask[dst];
    const ParSet& pp = P.s[b];

    // D0 row spread over 16 lanes
    float dq = __ldg(wig + (size_t)eg * 256 + q);

    // edge scalars (2 per lane)
    int zs = zn[src], zt = zn[dst];
    float dd = dist[eg];
    float z0 = dd * __ldg(pp.w_d + q)      + __ldg(pp.emb_s + zs * 32 + q)      + __ldg(pp.emb_t + zt * 32 + q);
    float z1 = dd * __ldg(pp.w_d + q + 16) + __ldg(pp.emb_s + zs * 32 + q + 16) + __ldg(pp.emb_t + zt * 32 + q + 16);
    float ev0 = z0 / (1.0f + expf(-z0));
    float ev1 = z1 / (1.0f + expf(-z1));

    const float4* As = (const float4*)(g_A + (size_t)src * 3072 + b * 1024);
    const float4* At = (const float4*)(g_A + (size_t)dst * 3072 + 2 * 1024);

    float4 acc = {0,0,0,0};
    #pragma unroll
    for (int n = 0; n < 16; n++) {
        float dn = __shfl_sync(0xffffffffu, dq, (le << 4) | n);
        float4 a1 = __ldg(As + n * 16 + q);
        float4 a2 = __ldg(At + n * 16 + q);
        acc.x += dn * (a1.x + a2.x);
        acc.y += dn * (a1.y + a2.y);
        acc.z += dn * (a1.z + a2.z);
        acc.w += dn * (a1.w + a2.w);
    }
    const float* sW = s_WeA + b * 2048;
    #pragma unroll 8
    for (int ce = 0; ce < 32; ce++) {
        float evv = __shfl_sync(0xffffffffu, (ce < 16) ? ev0 : ev1, (le << 4) | (ce & 15));
        float4 w = *(const float4*)(sW + ce * 64 + q * 4);
        acc.x += evv * w.x; acc.y += evv * w.y; acc.z += evv * w.z; acc.w += evv * w.w;
    }
    // leaky_relu * va, reduce to per-head logits
    float4 vv = __ldg((const float4*)(pp.va + q * 4));
    float a0 = ((acc.x > 0.f) ? acc.x : 0.2f * acc.x) * vv.x;
    float a1 = ((acc.y > 0.f) ? acc.y : 0.2f * acc.y) * vv.y;
    float a2 = ((acc.z > 0.f) ? acc.z : 0.2f * acc.z) * vv.z;
    float a3 = ((acc.w > 0.f) ? acc.w : 0.2f * acc.w) * vv.w;
    float s = a0 + a1 + a2 + a3;
    s += __shfl_xor_sync(0xffffffffu, s, 1);
    if ((q & 1) == 0) {
        int head = q >> 1;
        float el = expf(s);
        g_eexp[eg * 8 + head] = el;
        atomicAdd(&g_expsum[dst * 8 + head], el);
    }
}

// ---------------- pass 2: alpha, folded values, scatter ----------------
__global__ __launch_bounds__(256)
void k_pass2(const int* __restrict__ zn, const float* __restrict__ dist,
             const int* __restrict__ ei, const float* __restrict__ wig,
             Par2 P, float* __restrict__ out) {
    __shared__ float s_We[2 * 2048];      // raw We, both sets, 16KB
    int tid = threadIdx.x;
    for (int i = tid * 4; i < 2048; i += 1024)
        *(float4*)(s_We + i) = __ldg((const float4*)(P.s[0].We + i));
    for (int i = tid * 4; i < 2048; i += 1024)
        *(float4*)(s_We + 2048 + i) = __ldg((const float4*)(P.s[1].We + i));
    __syncthreads();

    int l  = tid & 31;
    int wid = tid >> 5;
    int le = l >> 4;
    int q  = l & 15;
    int eg = blockIdx.x * 16 + wid * 2 + le;

    int src = ei[eg], dst = ei[NE + eg];
    int b = g_mask[dst];
    const ParSet& pp = P.s[b];

    // alpha on lanes q<8
    float al = 0.0f;
    if (q < 8)
        al = g_eexp[eg * 8 + q] / (g_expsum[dst * 8 + q] + 1e-9f);

    // p[h4..h4+3] = sum_hd Ut[hd][h]*alpha[hd]
    float4 p = {0,0,0,0};
    #pragma unroll
    for (int hd = 0; hd < 8; hd++) {
        float av = __shfl_sync(0xffffffffu, al, (le << 4) | hd);
        float4 u = __ldg((const float4*)(&g_Ut[b][hd * 64 + q * 4]));
        p.x += av * u.x; p.y += av * u.y; p.z += av * u.z; p.w += av * u.w;
    }

    // edge scalars
    int zs = zn[src], zt = zn[dst];
    float dd = dist[eg];
    float z0 = dd * __ldg(pp.w_d + q)      + __ldg(pp.emb_s + zs * 32 + q)      + __ldg(pp.emb_t + zt * 32 + q);
    float z1 = dd * __ldg(pp.w_d + q + 16) + __ldg(pp.emb_s + zs * 32 + q + 16) + __ldg(pp.emb_t + zt * 32 + q + 16);
    float ev0 = z0 / (1.0f + expf(-z0));
    float ev1 = z1 / (1.0f + expf(-z1));

    // inj[h] = ev @ We
    const float* sW = s_We + b * 2048;
    float4 inj = {0,0,0,0};
    #pragma unroll 8
    for (int ce = 0; ce < 32; ce++) {
        float evv = __shfl_sync(0xffffffffu, (ce < 16) ? ev0 : ev1, (le << 4) | (ce & 15));
        float4 w = *(const float4*)(sW + ce * 64 + q * 4);
        inj.x += evv * w.x; inj.y += evv * w.y; inj.z += evv * w.z; inj.w += evv * w.w;
    }
    float pinj = p.x * inj.x + p.y * inj.y + p.z * inj.z + p.w * inj.w;

    // output rows via Y3
    const float4* Ys = (const float4*)(g_Y3 + (size_t)src * 576 + b * 192);
    const float4* Yt = (const float4*)(g_Y3 + (size_t)dst * 576 + 2 * 192);
    float o[3];
    #pragma unroll
    for (int r = 0; r < 3; r++) {
        float4 y1 = __ldg(Ys + r * 16 + q);
        float4 y2 = __ldg(Yt + r * 16 + q);
        o[r] = p.x * (y1.x + y2.x) + p.y * (y1.y + y2.y)
             + p.z * (y1.z + y2.z) + p.w * (y1.w + y2.w);
    }

    // reduce 4 scalars over 16-lane group
    #pragma unroll
    for (int off = 8; off; off >>= 1) {
        o[0] += __shfl_down_sync(0xffffffffu, o[0], off, 16);
        o[1] += __shfl_down_sync(0xffffffffu, o[1], off, 16);
        o[2] += __shfl_down_sync(0xffffffffu, o[2], off, 16);
        pinj += __shfl_down_sync(0xffffffffu, pinj, off, 16);
    }
    if (q == 0) {
        float d1 = __ldg(wig + (size_t)eg * 256 + 1);
        float d2 = __ldg(wig + (size_t)eg * 256 + 2);
        float d3 = __ldg(wig + (size_t)eg * 256 + 3);
        atomicAdd(&out[dst * 3 + 0], o[0] + pinj * d1);
        atomicAdd(&out[dst * 3 + 1], o[1] + pinj * d2);
        atomicAdd(&out[dst * 3 + 2], o[2] + pinj * d3);
    }
}

extern "C" void kernel_launch(void* const* d_in, const int* in_sizes, int n_in,
                              void* d_out, int out_size) {
    const float* x    = (const float*)d_in[0];
    const int*   zn   = (const int*)d_in[1];
    const float* dist = (const float*)d_in[2];
    const int*   ei   = (const int*)d_in[3];
    const void*  nm   = d_in[4];
    const float* wig  = (const float*)d_in[5];

    Par2 P;
    for (int s = 0; s < 2; s++) {
        int base = 6 + s * 10;
        P.s[s].emb_s = (const float*)d_in[base + 0];
        P.s[s].emb_t = (const float*)d_in[base + 1];
        P.s[s].w_d   = (const float*)d_in[base + 2];
        P.s[s].We    = (const float*)d_in[base + 3];
        P.s[s].Ws    = (const float*)d_in[base + 4];
        P.s[s].Wt    = (const float*)d_in[base + 5];
        P.s[s].Wa    = (const float*)d_in[base + 6];
        P.s[s].va    = (const float*)d_in[base + 7];
        P.s[s].Wv    = (const float*)d_in[base + 8];
        P.s[s].Wo    = (const float*)d_in[base + 9];
    }
    float* out = (float*)d_out;

    k_mask<<<1, 1024>>>(nm);
    k_small<<<64, 256>>>(P, out);
    k_node<<<NN, 256>>>(x, P);
    k_pass1<<<NE / 16, 256>>>(zn, dist, ei, wig, P);
    k_pass2<<<NE / 16, 256>>>(zn, dist, ei, wig, P, out);
}